// round 7
// baseline (speedup 1.0000x reference)
#include <cuda_runtime.h>
#include <math.h>

#define N       12288
#define D_K     8
#define H1      32
#define H2      16
#define N_EDGES 6144
#define N_TRI   4096
#define CAP     64
#define ECAP    32
#define NB      192
#define TPB     512
#define RPB     64    // rows per block (TPB/8)

// ---------------- device scratch (zero-initialized at module load) ----------------
__device__ float    g_k[N * D_K];
__device__ float    g_v[N * D_K];
__device__ float    g_logits[N];
__device__ int      g_cnt[N_TRI];           // zeroed at end of each call
__device__ int      g_mem[N_TRI * CAP];
__device__ int      g_ecnt[N_EDGES];        // zeroed at end of each call
__device__ int      g_emem[N_EDGES * ECAP];
__device__ unsigned g_bar1, g_bar2, g_bar3; // reset at end of each call

__device__ __forceinline__ float gelu_exact(float x) {
    return 0.5f * x * (1.0f + erff(x * 0.70710678118654752f));
}

// software grid barrier — safe: launch_bounds(512,2) guarantees 2 blocks/SM
// schedulability, so 192 blocks <= 148*2 = one co-resident wave.
__device__ __forceinline__ void grid_barrier(unsigned* ctr) {
    __syncthreads();
    if (threadIdx.x == 0) {
        __threadfence();
        atomicAdd(ctr, 1u);
        while (*(volatile unsigned*)ctr < NB) {}
        __threadfence();
    }
    __syncthreads();
}

__global__ __launch_bounds__(TPB, 2)
void k_fused(const float* __restrict__ ef, const int* __restrict__ eids,
             const int* __restrict__ tri,
             const float* __restrict__ Wq, const float* __restrict__ bq,
             const float* __restrict__ Wk, const float* __restrict__ bk,
             const float* __restrict__ Wv, const float* __restrict__ bv,
             const float* __restrict__ W1, const float* __restrict__ b1,
             const float* __restrict__ ln1g, const float* __restrict__ ln1b,
             const float* __restrict__ rmsw,
             const float* __restrict__ Wr, const float* __restrict__ br,
             const float* __restrict__ ln2g, const float* __restrict__ ln2b,
             const float* __restrict__ W2, const float* __restrict__ b2,
             const float* __restrict__ W3, const float* __restrict__ b3,
             float* __restrict__ out) {
    // padded shared weights (odd strides -> conflict-free)
    __shared__ float sW1[H1 * 9];        // [o*9 + k], k<8
    __shared__ float sWr[H1 * 33];       // [o*33 + k], k<32
    __shared__ float sW2[H2 * 33];       // [o*33 + k], k<32
    __shared__ float sb1[H1], sg1[H1], sB1[H1], srw[H1], sbr[H1], sg2[H1], sB2[H1];
    __shared__ float sb2[H2], sW3[H2];
    __shared__ float sb3;
    __shared__ float sh[RPB * 33];       // per-row 32-vector scratch, padded

    const int tid = threadIdx.x;
    const int sub = tid & 7;             // lane within 8-lane row group
    const int rl  = tid >> 3;            // local row
    const int i   = blockIdx.x * RPB + rl;
    const int lane = tid & 31;
    const unsigned gmask = 0xFFu << (lane & ~7);  // this group's shuffle mask

    // ---- stage weights (overlaps phase 1) ----
    for (int j = tid; j < H1 * D_K; j += TPB) sW1[(j >> 3) * 9  + (j & 7)]  = W1[j];
    for (int j = tid; j < H1 * H1;  j += TPB) sWr[(j >> 5) * 33 + (j & 31)] = Wr[j];
    for (int j = tid; j < H2 * H1;  j += TPB) sW2[(j >> 5) * 33 + (j & 31)] = W2[j];
    if (tid < H1) {
        sb1[tid] = b1[tid];   sg1[tid] = ln1g[tid]; sB1[tid] = ln1b[tid];
        srw[tid] = rmsw[tid]; sbr[tid] = br[tid];
        sg2[tid] = ln2g[tid]; sB2[tid] = ln2b[tid];
    }
    if (tid < H2) { sb2[tid] = b2[tid]; sW3[tid] = W3[tid]; }
    if (tid == 0) sb3 = b3[0];

    // ================= Phase 1: qkv (1 dim/lane) + bucketing =================
    float qd;                             // this lane's q dim, kept live
    {
        float x0 = ef[2 * i + 0];
        float x1 = ef[2 * i + 1];
        qd       = fmaf(x0, Wq[sub * 2], fmaf(x1, Wq[sub * 2 + 1], bq[sub]));
        float kd = fmaf(x0, Wk[sub * 2], fmaf(x1, Wk[sub * 2 + 1], bk[sub]));
        float vd = fmaf(x0, Wv[sub * 2], fmaf(x1, Wv[sub * 2 + 1], bv[sub]));
        g_k[i * D_K + sub] = kd;
        g_v[i * D_K + sub] = vd;
        if (sub == 0) {
            int t = tri[i];
            int p = atomicAdd(&g_cnt[t], 1);
            if (p < CAP) g_mem[t * CAP + p] = i;
            int e  = eids[i];
            int pe = atomicAdd(&g_ecnt[e], 1);
            if (pe < ECAP) g_emem[e * ECAP + pe] = i;
        }
    }

    grid_barrier(&g_bar1);

    // ================= Phase 2: attention + MLP -> logits =================
    {
        // full q[8] to every lane via intra-group broadcast
        float q[D_K];
#pragma unroll
        for (int s2 = 0; s2 < D_K; s2++) q[s2] = __shfl_sync(gmask, qd, s2, 8);

        int t = tri[i];
        int c = min(g_cnt[t], CAP);
        const float isq = 0.35355339059327373f;  // 1/sqrt(8)

        // members distributed across 8 lanes; full dot per lane; one-pass softmax
        float se = 0.0f, acc[D_K];
#pragma unroll
        for (int o = 0; o < D_K; o++) acc[o] = 0.0f;
        for (int jj = sub; jj < c; jj += 8) {
            int j = g_mem[t * CAP + jj];
            float4 ka = ((const float4*)g_k)[j * 2];
            float4 kb = ((const float4*)g_k)[j * 2 + 1];
            float4 va = ((const float4*)g_v)[j * 2];
            float4 vb = ((const float4*)g_v)[j * 2 + 1];
            float p = q[0]*ka.x + q[1]*ka.y + q[2]*ka.z + q[3]*ka.w
                    + q[4]*kb.x + q[5]*kb.y + q[6]*kb.z + q[7]*kb.w;
            float e = expf(p * isq);     // scores bounded; normalization identical
            se += e;
            acc[0] = fmaf(e, va.x, acc[0]); acc[1] = fmaf(e, va.y, acc[1]);
            acc[2] = fmaf(e, va.z, acc[2]); acc[3] = fmaf(e, va.w, acc[3]);
            acc[4] = fmaf(e, vb.x, acc[4]); acc[5] = fmaf(e, vb.y, acc[5]);
            acc[6] = fmaf(e, vb.z, acc[6]); acc[7] = fmaf(e, vb.w, acc[7]);
        }
        // cross-lane reduction over 8 lanes (independent shuffles pipeline)
        se += __shfl_xor_sync(gmask, se, 1);
        se += __shfl_xor_sync(gmask, se, 2);
        se += __shfl_xor_sync(gmask, se, 4);
#pragma unroll
        for (int o = 0; o < D_K; o++) {
            acc[o] += __shfl_xor_sync(gmask, acc[o], 1);
            acc[o] += __shfl_xor_sync(gmask, acc[o], 2);
            acc[o] += __shfl_xor_sync(gmask, acc[o], 4);
        }
        float inv_se = 1.0f / se;
        float att[D_K];
#pragma unroll
        for (int o = 0; o < D_K; o++) att[o] = acc[o] * inv_se;

        // ---- MLP: this lane owns outputs o = 4*sub .. 4*sub+3 ----
        const int ob = 4 * sub;
        float h[4];
#pragma unroll
        for (int oi = 0; oi < 4; oi++) {
            int o = ob + oi;
            float s = sb1[o];
#pragma unroll
            for (int kk = 0; kk < D_K; kk++) s = fmaf(att[kk], sW1[o * 9 + kk], s);
            h[oi] = s;
        }
        // layernorm 1 + gelu
        {
            float ls = h[0] + h[1] + h[2] + h[3];
            ls += __shfl_xor_sync(gmask, ls, 1);
            ls += __shfl_xor_sync(gmask, ls, 2);
            ls += __shfl_xor_sync(gmask, ls, 4);
            float mu = ls * (1.0f / H1);
            float lv = 0.0f;
#pragma unroll
            for (int oi = 0; oi < 4; oi++) { float d = h[oi] - mu; lv = fmaf(d, d, lv); }
            lv += __shfl_xor_sync(gmask, lv, 1);
            lv += __shfl_xor_sync(gmask, lv, 2);
            lv += __shfl_xor_sync(gmask, lv, 4);
            float inv = rsqrtf(lv * (1.0f / H1) + 1e-5f);
#pragma unroll
            for (int oi = 0; oi < 4; oi++)
                h[oi] = gelu_exact((h[oi] - mu) * inv * sg1[ob + oi] + sB1[ob + oi]);
        }
        // rmsnorm -> shared -> linear -> relu -> residual
        {
            float ss = 0.0f;
#pragma unroll
            for (int oi = 0; oi < 4; oi++) ss = fmaf(h[oi], h[oi], ss);
            ss += __shfl_xor_sync(gmask, ss, 1);
            ss += __shfl_xor_sync(gmask, ss, 2);
            ss += __shfl_xor_sync(gmask, ss, 4);
            float rms = sqrtf(ss * (1.0f / H1));
            float rinv = 1.0f / (rms + 1e-6f);
#pragma unroll
            for (int oi = 0; oi < 4; oi++)
                sh[rl * 33 + ob + oi] = h[oi] * rinv * srw[ob + oi];
            __syncwarp();
#pragma unroll
            for (int oi = 0; oi < 4; oi++) {
                int o = ob + oi;
                float s = sbr[o];
#pragma unroll
                for (int kk = 0; kk < H1; kk++)
                    s = fmaf(sh[rl * 33 + kk], sWr[o * 33 + kk], s);
                h[oi] += fmaxf(s, 0.0f);
            }
        }
        // layernorm 2
        {
            float ls = h[0] + h[1] + h[2] + h[3];
            ls += __shfl_xor_sync(gmask, ls, 1);
            ls += __shfl_xor_sync(gmask, ls, 2);
            ls += __shfl_xor_sync(gmask, ls, 4);
            float mu = ls * (1.0f / H1);
            float lv = 0.0f;
#pragma unroll
            for (int oi = 0; oi < 4; oi++) { float d = h[oi] - mu; lv = fmaf(d, d, lv); }
            lv += __shfl_xor_sync(gmask, lv, 1);
            lv += __shfl_xor_sync(gmask, lv, 2);
            lv += __shfl_xor_sync(gmask, lv, 4);
            float inv = rsqrtf(lv * (1.0f / H1) + 1e-5f);
#pragma unroll
            for (int oi = 0; oi < 4; oi++)
                h[oi] = (h[oi] - mu) * inv * sg2[ob + oi] + sB2[ob + oi];
        }
        // publish h, then linear 32->16 + gelu + linear 16->1 (2 outputs/lane)
        __syncwarp();
#pragma unroll
        for (int oi = 0; oi < 4; oi++) sh[rl * 33 + ob + oi] = h[oi];
        __syncwarp();
        float part = 0.0f;
#pragma unroll
        for (int oi = 0; oi < 2; oi++) {
            int o = 2 * sub + oi;
            float s = sb2[o];
#pragma unroll
            for (int kk = 0; kk < H1; kk++)
                s = fmaf(sh[rl * 33 + kk], sW2[o * 33 + kk], s);
            part = fmaf(gelu_exact(s), sW3[o], part);
        }
        part += __shfl_xor_sync(gmask, part, 1);
        part += __shfl_xor_sync(gmask, part, 2);
        part += __shfl_xor_sync(gmask, part, 4);
        if (sub == 0) g_logits[i] = part + sb3;
    }

    grid_barrier(&g_bar2);

    // ================= Phase 3: per-edge-segment softmax (32 edges/block) ====
    if (tid < 32) {
        int e = blockIdx.x * 32 + tid;
        int c = min(g_ecnt[e], ECAP);
        g_ecnt[e] = 0;                         // reset for next replay
        if (c > 0) {
            float mx = -1e30f;
            for (int jj = 0; jj < c; jj++)
                mx = fmaxf(mx, g_logits[g_emem[e * ECAP + jj]]);
            float sum = 0.0f;
            for (int jj = 0; jj < c; jj++)
                sum += expf(g_logits[g_emem[e * ECAP + jj]] - mx);
            float inv = 1.0f / sum;
            for (int jj = 0; jj < c; jj++) {
                int j = g_emem[e * ECAP + jj];
                out[j] = expf(g_logits[j] - mx) * inv;
            }
        }
    }
    {
        int gtid = blockIdx.x * TPB + tid;
        if (gtid < N_TRI) g_cnt[gtid] = 0;     // reset for next replay
    }

    // ---- final arrival: last block resets barrier counters ----
    __syncthreads();
    if (tid == 0) {
        __threadfence();
        unsigned prev = atomicAdd(&g_bar3, 1u);
        if (prev == NB - 1u) {
            g_bar1 = 0u; g_bar2 = 0u; g_bar3 = 0u;
            __threadfence();
        }
    }
}

extern "C" void kernel_launch(void* const* d_in, const int* in_sizes, int n_in,
                              void* d_out, int out_size) {
    const float* ef   = (const float*)d_in[0];
    const int*   eids = (const int*)  d_in[1];
    const int*   tri  = (const int*)  d_in[2];
    const float* Wq = (const float*)d_in[3];  const float* bq = (const float*)d_in[4];
    const float* Wk = (const float*)d_in[5];  const float* bk = (const float*)d_in[6];
    const float* Wv = (const float*)d_in[7];  const float* bv = (const float*)d_in[8];
    const float* W1 = (const float*)d_in[9];  const float* b1 = (const float*)d_in[10];
    const float* g1 = (const float*)d_in[11]; const float* B1 = (const float*)d_in[12];
    const float* rw = (const float*)d_in[13];
    const float* Wr = (const float*)d_in[14]; const float* br = (const float*)d_in[15];
    const float* g2 = (const float*)d_in[16]; const float* B2 = (const float*)d_in[17];
    const float* W2 = (const float*)d_in[18]; const float* b2 = (const float*)d_in[19];
    const float* W3 = (const float*)d_in[20]; const float* b3 = (const float*)d_in[21];
    float* out = (float*)d_out;

    k_fused<<<NB, TPB>>>(ef, eids, tri, Wq, bq, Wk, bk, Wv, bv,
                         W1, b1, g1, B1, rw, Wr, br, g2, B2, W2, b2, W3, b3, out);
}

// round 8
// speedup vs baseline: 1.1596x; 1.1596x over previous
#include <cuda_runtime.h>
#include <math.h>

#define N       12288
#define D_K     8
#define H1      32
#define H2      16
#define N_EDGES 6144
#define N_TRI   4096
#define CAP     64
#define ECAP    32
#define NB      128
#define TPB     384
#define RPB     96    // rows per block (TPB/4)
#define EPB     48    // edges per block in phase 3 (N_EDGES/NB)

// ---------------- device scratch (zero-initialized at module load) ----------------
__device__ float    g_k[N * D_K];
__device__ float    g_v[N * D_K];
__device__ float    g_logits[N];
__device__ int      g_cnt[N_TRI];           // zeroed at end of each call
__device__ int      g_mem[N_TRI * CAP];
__device__ int      g_ecnt[N_EDGES];        // zeroed at end of each call
__device__ int      g_emem[N_EDGES * ECAP];
__device__ unsigned g_bar1, g_bar2, g_bar3; // reset at end of each call

__device__ __forceinline__ float gelu_exact(float x) {
    return 0.5f * x * (1.0f + erff(x * 0.70710678118654752f));
}

// software grid barrier — safe: 128 blocks, 1 block/SM, single wave on 148 SMs
__device__ __forceinline__ void grid_barrier(unsigned* ctr) {
    __syncthreads();
    if (threadIdx.x == 0) {
        __threadfence();
        atomicAdd(ctr, 1u);
        while (*(volatile unsigned*)ctr < NB) {}
        __threadfence();
    }
    __syncthreads();
}

__global__ __launch_bounds__(TPB, 1)
void k_fused(const float* __restrict__ ef, const int* __restrict__ eids,
             const int* __restrict__ tri,
             const float* __restrict__ Wq, const float* __restrict__ bq,
             const float* __restrict__ Wk, const float* __restrict__ bk,
             const float* __restrict__ Wv, const float* __restrict__ bv,
             const float* __restrict__ W1, const float* __restrict__ b1,
             const float* __restrict__ ln1g, const float* __restrict__ ln1b,
             const float* __restrict__ rmsw,
             const float* __restrict__ Wr, const float* __restrict__ br,
             const float* __restrict__ ln2g, const float* __restrict__ ln2b,
             const float* __restrict__ W2, const float* __restrict__ b2,
             const float* __restrict__ W3, const float* __restrict__ b3,
             float* __restrict__ out) {
    // padded shared weights (odd strides -> conflict-free for 4-lane groups)
    __shared__ float sW1[H1 * 9];        // [o*9 + k], k<8
    __shared__ float sWr[H1 * 33];       // [o*33 + k], k<32
    __shared__ float sW2[H2 * 33];       // [o*33 + k], k<32
    __shared__ float sb1[H1], sg1[H1], sB1[H1], srw[H1], sbr[H1], sg2[H1], sB2[H1];
    __shared__ float sb2[H2], sW3[H2];
    __shared__ float sb3;
    __shared__ float sh[RPB * 33];       // per-row 32-vector scratch, padded

    const int tid = threadIdx.x;
    const int sub = tid & 3;             // lane within 4-lane row group
    const int rl  = tid >> 2;            // local row
    const int i   = blockIdx.x * RPB + rl;
    const int lane = tid & 31;
    const unsigned gmask = 0xFu << (lane & ~3);   // this group's shuffle mask

    // ---- stage weights (overlaps phase 1) ----
    for (int j = tid; j < H1 * D_K; j += TPB) sW1[(j >> 3) * 9  + (j & 7)]  = W1[j];
    for (int j = tid; j < H1 * H1;  j += TPB) sWr[(j >> 5) * 33 + (j & 31)] = Wr[j];
    for (int j = tid; j < H2 * H1;  j += TPB) sW2[(j >> 5) * 33 + (j & 31)] = W2[j];
    if (tid < H1) {
        sb1[tid] = b1[tid];   sg1[tid] = ln1g[tid]; sB1[tid] = ln1b[tid];
        srw[tid] = rmsw[tid]; sbr[tid] = br[tid];
        sg2[tid] = ln2g[tid]; sB2[tid] = ln2b[tid];
    }
    if (tid < H2) { sb2[tid] = b2[tid]; sW3[tid] = W3[tid]; }
    if (tid == 0) sb3 = b3[0];

    // ================= Phase 1: qkv (2 dims/lane) + bucketing =================
    float2 qv;                            // kept live for phase 2
    {
        float x0 = ef[2 * i + 0];
        float x1 = ef[2 * i + 1];
        int o0 = 2 * sub;
        float2 kv, vv;
        qv.x = fmaf(x0, Wq[o0*2],     fmaf(x1, Wq[o0*2+1],     bq[o0]));
        qv.y = fmaf(x0, Wq[(o0+1)*2], fmaf(x1, Wq[(o0+1)*2+1], bq[o0+1]));
        kv.x = fmaf(x0, Wk[o0*2],     fmaf(x1, Wk[o0*2+1],     bk[o0]));
        kv.y = fmaf(x0, Wk[(o0+1)*2], fmaf(x1, Wk[(o0+1)*2+1], bk[o0+1]));
        vv.x = fmaf(x0, Wv[o0*2],     fmaf(x1, Wv[o0*2+1],     bv[o0]));
        vv.y = fmaf(x0, Wv[(o0+1)*2], fmaf(x1, Wv[(o0+1)*2+1], bv[o0+1]));
        ((float2*)g_k)[i * 4 + sub] = kv;
        ((float2*)g_v)[i * 4 + sub] = vv;
        if (sub == 0) {
            int t = tri[i];
            int p = atomicAdd(&g_cnt[t], 1);
            if (p < CAP) g_mem[t * CAP + p] = i;
            int e  = eids[i];
            int pe = atomicAdd(&g_ecnt[e], 1);
            if (pe < ECAP) g_emem[e * ECAP + pe] = i;
        }
    }

    grid_barrier(&g_bar1);

    // ================= Phase 2: attention + MLP -> logits =================
    {
        // full q[8] to every lane via intra-group broadcast
        float q[D_K];
#pragma unroll
        for (int s2 = 0; s2 < 4; s2++) {
            q[2*s2]   = __shfl_sync(gmask, qv.x, s2, 4);
            q[2*s2+1] = __shfl_sync(gmask, qv.y, s2, 4);
        }

        int t = tri[i];
        int c = min(g_cnt[t], CAP);
        const float isq = 0.35355339059327373f;  // 1/sqrt(8)

        // members distributed across the 4 lanes; full dot per lane; one-pass softmax
        float se = 0.0f, acc[D_K];
#pragma unroll
        for (int o = 0; o < D_K; o++) acc[o] = 0.0f;
        for (int jj = sub; jj < c; jj += 4) {
            int j = g_mem[t * CAP + jj];
            float4 ka = ((const float4*)g_k)[j * 2];
            float4 kb = ((const float4*)g_k)[j * 2 + 1];
            float4 va = ((const float4*)g_v)[j * 2];
            float4 vb = ((const float4*)g_v)[j * 2 + 1];
            float p = q[0]*ka.x + q[1]*ka.y + q[2]*ka.z + q[3]*ka.w
                    + q[4]*kb.x + q[5]*kb.y + q[6]*kb.z + q[7]*kb.w;
            float e = expf(p * isq);     // scores bounded; normalization identical
            se += e;
            acc[0] = fmaf(e, va.x, acc[0]); acc[1] = fmaf(e, va.y, acc[1]);
            acc[2] = fmaf(e, va.z, acc[2]); acc[3] = fmaf(e, va.w, acc[3]);
            acc[4] = fmaf(e, vb.x, acc[4]); acc[5] = fmaf(e, vb.y, acc[5]);
            acc[6] = fmaf(e, vb.z, acc[6]); acc[7] = fmaf(e, vb.w, acc[7]);
        }
        se += __shfl_xor_sync(gmask, se, 1);
        se += __shfl_xor_sync(gmask, se, 2);
#pragma unroll
        for (int o = 0; o < D_K; o++) {
            acc[o] += __shfl_xor_sync(gmask, acc[o], 1);
            acc[o] += __shfl_xor_sync(gmask, acc[o], 2);
        }
        float inv_se = 1.0f / se;
        float att[D_K];
#pragma unroll
        for (int o = 0; o < D_K; o++) att[o] = acc[o] * inv_se;

        // ---- MLP: this lane owns outputs o = 8*sub .. 8*sub+7 ----
        const int ob = 8 * sub;
        float h[8];
#pragma unroll
        for (int oi = 0; oi < 8; oi++) {
            int o = ob + oi;
            float s = sb1[o];
#pragma unroll
            for (int kk = 0; kk < D_K; kk++) s = fmaf(att[kk], sW1[o * 9 + kk], s);
            h[oi] = s;
        }
        // layernorm 1 + gelu
        {
            float ls = 0.0f;
#pragma unroll
            for (int oi = 0; oi < 8; oi++) ls += h[oi];
            ls += __shfl_xor_sync(gmask, ls, 1);
            ls += __shfl_xor_sync(gmask, ls, 2);
            float mu = ls * (1.0f / H1);
            float lv = 0.0f;
#pragma unroll
            for (int oi = 0; oi < 8; oi++) { float d = h[oi] - mu; lv = fmaf(d, d, lv); }
            lv += __shfl_xor_sync(gmask, lv, 1);
            lv += __shfl_xor_sync(gmask, lv, 2);
            float inv = rsqrtf(lv * (1.0f / H1) + 1e-5f);
#pragma unroll
            for (int oi = 0; oi < 8; oi++)
                h[oi] = gelu_exact((h[oi] - mu) * inv * sg1[ob + oi] + sB1[ob + oi]);
        }
        // rmsnorm -> shared -> linear -> relu -> residual
        {
            float ss = 0.0f;
#pragma unroll
            for (int oi = 0; oi < 8; oi++) ss = fmaf(h[oi], h[oi], ss);
            ss += __shfl_xor_sync(gmask, ss, 1);
            ss += __shfl_xor_sync(gmask, ss, 2);
            float rms = sqrtf(ss * (1.0f / H1));
            float rinv = 1.0f / (rms + 1e-6f);
#pragma unroll
            for (int oi = 0; oi < 8; oi++)
                sh[rl * 33 + ob + oi] = h[oi] * rinv * srw[ob + oi];
            __syncwarp();
#pragma unroll
            for (int oi = 0; oi < 8; oi++) {
                int o = ob + oi;
                float s = sbr[o];
#pragma unroll
                for (int kk = 0; kk < H1; kk++)
                    s = fmaf(sh[rl * 33 + kk], sWr[o * 33 + kk], s);
                h[oi] += fmaxf(s, 0.0f);
            }
        }
        // layernorm 2
        {
            float ls = 0.0f;
#pragma unroll
            for (int oi = 0; oi < 8; oi++) ls += h[oi];
            ls += __shfl_xor_sync(gmask, ls, 1);
            ls += __shfl_xor_sync(gmask, ls, 2);
            float mu = ls * (1.0f / H1);
            float lv = 0.0f;
#pragma unroll
            for (int oi = 0; oi < 8; oi++) { float d = h[oi] - mu; lv = fmaf(d, d, lv); }
            lv += __shfl_xor_sync(gmask, lv, 1);
            lv += __shfl_xor_sync(gmask, lv, 2);
            float inv = rsqrtf(lv * (1.0f / H1) + 1e-5f);
#pragma unroll
            for (int oi = 0; oi < 8; oi++)
                h[oi] = (h[oi] - mu) * inv * sg2[ob + oi] + sB2[ob + oi];
        }
        // publish h, then linear 32->16 + gelu + linear 16->1 (4 outputs/lane)
        __syncwarp();
#pragma unroll
        for (int oi = 0; oi < 8; oi++) sh[rl * 33 + ob + oi] = h[oi];
        __syncwarp();
        float part = 0.0f;
#pragma unroll
        for (int oi = 0; oi < 4; oi++) {
            int o = 4 * sub + oi;
            float s = sb2[o];
#pragma unroll
            for (int kk = 0; kk < H1; kk++)
                s = fmaf(sh[rl * 33 + kk], sW2[o * 33 + kk], s);
            part = fmaf(gelu_exact(s), sW3[o], part);
        }
        part += __shfl_xor_sync(gmask, part, 1);
        part += __shfl_xor_sync(gmask, part, 2);
        if (sub == 0) g_logits[i] = part + sb3;
    }

    grid_barrier(&g_bar2);

    // ================= Phase 3: per-edge-segment softmax (48 edges/block) ====
    if (tid < EPB) {
        int e = blockIdx.x * EPB + tid;
        int c = min(g_ecnt[e], ECAP);
        g_ecnt[e] = 0;                         // reset for next replay
        if (c > 0) {
            float mx = -1e30f;
            for (int jj = 0; jj < c; jj++)
                mx = fmaxf(mx, g_logits[g_emem[e * ECAP + jj]]);
            float sum = 0.0f;
            for (int jj = 0; jj < c; jj++)
                sum += expf(g_logits[g_emem[e * ECAP + jj]] - mx);
            float inv = 1.0f / sum;
            for (int jj = 0; jj < c; jj++) {
                int j = g_emem[e * ECAP + jj];
                out[j] = expf(g_logits[j] - mx) * inv;
            }
        }
    }
    {
        int gtid = blockIdx.x * TPB + tid;     // blocks 0..10 cover 4096
        if (gtid < N_TRI) g_cnt[gtid] = 0;     // reset for next replay
    }

    // ---- final arrival: last block resets barrier counters ----
    __syncthreads();
    if (tid == 0) {
        __threadfence();
        unsigned prev = atomicAdd(&g_bar3, 1u);
        if (prev == NB - 1u) {
            g_bar1 = 0u; g_bar2 = 0u; g_bar3 = 0u;
            __threadfence();
        }
    }
}

extern "C" void kernel_launch(void* const* d_in, const int* in_sizes, int n_in,
                              void* d_out, int out_size) {
    const float* ef   = (const float*)d_in[0];
    const int*   eids = (const int*)  d_in[1];
    const int*   tri  = (const int*)  d_in[2];
    const float* Wq = (const float*)d_in[3];  const float* bq = (const float*)d_in[4];
    const float* Wk = (const float*)d_in[5];  const float* bk = (const float*)d_in[6];
    const float* Wv = (const float*)d_in[7];  const float* bv = (const float*)d_in[8];
    const float* W1 = (const float*)d_in[9];  const float* b1 = (const float*)d_in[10];
    const float* g1 = (const float*)d_in[11]; const float* B1 = (const float*)d_in[12];
    const float* rw = (const float*)d_in[13];
    const float* Wr = (const float*)d_in[14]; const float* br = (const float*)d_in[15];
    const float* g2 = (const float*)d_in[16]; const float* B2 = (const float*)d_in[17];
    const float* W2 = (const float*)d_in[18]; const float* b2 = (const float*)d_in[19];
    const float* W3 = (const float*)d_in[20]; const float* b3 = (const float*)d_in[21];
    float* out = (float*)d_out;

    k_fused<<<NB, TPB>>>(ef, eids, tri, Wq, bq, Wk, bk, Wv, bv,
                         W1, b1, g1, B1, rw, Wr, br, g2, B2, W2, b2, W3, b3, out);
}

// round 9
// speedup vs baseline: 1.3619x; 1.1745x over previous
#include <cuda_runtime.h>
#include <math.h>

#define N       12288
#define D_K     8
#define H1      32
#define H2      16
#define N_EDGES 6144
#define N_TRI   4096
#define CAP     64
#define ECAP    32
#define NB      128
#define TPB     384
#define RPB     96    // rows per block (TPB/4)

// ---------------- device scratch (zero-initialized at module load) ----------------
__device__ float    g_k[N * D_K];
__device__ float    g_v[N * D_K];
__device__ float    g_logits[N];
__device__ int      g_cnt[N_TRI];           // returns to 0 every call (tri completion)
__device__ int      g_tdone[N_TRI];         // returns to 0 every call
__device__ int      g_mem[N_TRI * CAP];
__device__ int      g_ecnt[N_EDGES];        // returns to 0 every call (edge completion)
__device__ int      g_edone[N_EDGES];       // returns to 0 every call
__device__ int      g_emem[N_EDGES * ECAP];
__device__ unsigned g_bar1;                 // monotonic ticket counter (never reset)

__device__ __forceinline__ float gelu_exact(float x) {
    return 0.5f * x * (1.0f + erff(x * 0.70710678118654752f));
}

// ticket grid barrier — monotonic across graph replays, no reset required.
// safe: 128 blocks, 1 block/SM, strictly one co-resident wave on 148 SMs.
__device__ __forceinline__ void grid_barrier_ticket(unsigned* ctr) {
    __syncthreads();
    if (threadIdx.x == 0) {
        __threadfence();
        unsigned t0 = atomicAdd(ctr, 1u);
        unsigned target = t0 - (t0 % NB) + NB;
        while (*(volatile unsigned*)ctr < target) {}
        __threadfence();
    }
    __syncthreads();
}

__global__ __launch_bounds__(TPB, 1)
void k_fused(const float* __restrict__ ef, const int* __restrict__ eids,
             const int* __restrict__ tri,
             const float* __restrict__ Wq, const float* __restrict__ bq,
             const float* __restrict__ Wk, const float* __restrict__ bk,
             const float* __restrict__ Wv, const float* __restrict__ bv,
             const float* __restrict__ W1, const float* __restrict__ b1,
             const float* __restrict__ ln1g, const float* __restrict__ ln1b,
             const float* __restrict__ rmsw,
             const float* __restrict__ Wr, const float* __restrict__ br,
             const float* __restrict__ ln2g, const float* __restrict__ ln2b,
             const float* __restrict__ W2, const float* __restrict__ b2,
             const float* __restrict__ W3, const float* __restrict__ b3,
             float* __restrict__ out) {
    // padded shared weights (odd strides -> conflict-free for 4-lane groups)
    __shared__ float sW1[H1 * 9];        // [o*9 + k], k<8
    __shared__ float sWr[H1 * 33];       // [o*33 + k], k<32
    __shared__ float sW2[H2 * 33];       // [o*33 + k], k<32
    __shared__ float sb1[H1], sg1[H1], sB1[H1], srw[H1], sbr[H1], sg2[H1], sB2[H1];
    __shared__ float sb2[H2], sW3[H2];
    __shared__ float sb3;
    __shared__ float sh[RPB * 33];       // per-row 32-vector scratch, padded

    const int tid = threadIdx.x;
    const int sub = tid & 3;             // lane within 4-lane row group
    const int rl  = tid >> 2;            // local row
    const int i   = blockIdx.x * RPB + rl;
    const int lane = tid & 31;
    const unsigned gmask = 0xFu << (lane & ~3);   // this group's shuffle mask

    // ---- stage weights (overlaps phase 1; consumed only after the barrier) ----
    for (int j = tid; j < H1 * D_K; j += TPB) sW1[(j >> 3) * 9  + (j & 7)]  = W1[j];
    for (int j = tid; j < H1 * H1;  j += TPB) sWr[(j >> 5) * 33 + (j & 31)] = Wr[j];
    for (int j = tid; j < H2 * H1;  j += TPB) sW2[(j >> 5) * 33 + (j & 31)] = W2[j];
    if (tid < H1) {
        sb1[tid] = b1[tid];   sg1[tid] = ln1g[tid]; sB1[tid] = ln1b[tid];
        srw[tid] = rmsw[tid]; sbr[tid] = br[tid];
        sg2[tid] = ln2g[tid]; sB2[tid] = ln2b[tid];
    }
    if (tid < H2) { sb2[tid] = b2[tid]; sW3[tid] = W3[tid]; }
    if (tid == 0) sb3 = b3[0];

    // ================= Phase 1: qkv (2 dims/lane) + bucketing =================
    float2 qv;                            // kept live for phase 2
    {
        float x0 = ef[2 * i + 0];
        float x1 = ef[2 * i + 1];
        int o0 = 2 * sub;
        float2 kv, vv;
        qv.x = fmaf(x0, Wq[o0*2],     fmaf(x1, Wq[o0*2+1],     bq[o0]));
        qv.y = fmaf(x0, Wq[(o0+1)*2], fmaf(x1, Wq[(o0+1)*2+1], bq[o0+1]));
        kv.x = fmaf(x0, Wk[o0*2],     fmaf(x1, Wk[o0*2+1],     bk[o0]));
        kv.y = fmaf(x0, Wk[(o0+1)*2], fmaf(x1, Wk[(o0+1)*2+1], bk[o0+1]));
        vv.x = fmaf(x0, Wv[o0*2],     fmaf(x1, Wv[o0*2+1],     bv[o0]));
        vv.y = fmaf(x0, Wv[(o0+1)*2], fmaf(x1, Wv[(o0+1)*2+1], bv[o0+1]));
        ((float2*)g_k)[i * 4 + sub] = kv;
        ((float2*)g_v)[i * 4 + sub] = vv;
        if (sub == 0) {
            int t = tri[i];
            int p = atomicAdd(&g_cnt[t], 1);
            if (p < CAP) g_mem[t * CAP + p] = i;
            int e  = eids[i];
            int pe = atomicAdd(&g_ecnt[e], 1);
            if (pe < ECAP) g_emem[e * ECAP + pe] = i;
        }
    }

    grid_barrier_ticket(&g_bar1);

    // ====== Phase 2: attention + MLP -> logits + dataflow completions ======
    {
        // full q[8] to every lane via intra-group broadcast
        float q[D_K];
#pragma unroll
        for (int s2 = 0; s2 < 4; s2++) {
            q[2*s2]   = __shfl_sync(gmask, qv.x, s2, 4);
            q[2*s2+1] = __shfl_sync(gmask, qv.y, s2, 4);
        }

        const int t  = tri[i];
        const int e  = eids[i];
        const int cc = g_cnt[t];             // final after barrier
        const int c  = min(cc, CAP);
        const int tot = g_ecnt[e];           // final after barrier
        const float isq = 0.35355339059327373f;  // 1/sqrt(8)

        // members distributed across 4 lanes; full dot per lane; one-pass softmax
        float se = 0.0f, acc[D_K];
#pragma unroll
        for (int o = 0; o < D_K; o++) acc[o] = 0.0f;
        for (int jj = sub; jj < c; jj += 4) {
            int j = g_mem[t * CAP + jj];
            float4 ka = ((const float4*)g_k)[j * 2];
            float4 kb = ((const float4*)g_k)[j * 2 + 1];
            float4 va = ((const float4*)g_v)[j * 2];
            float4 vb = ((const float4*)g_v)[j * 2 + 1];
            float p = q[0]*ka.x + q[1]*ka.y + q[2]*ka.z + q[3]*ka.w
                    + q[4]*kb.x + q[5]*kb.y + q[6]*kb.z + q[7]*kb.w;
            float ex = __expf(p * isq);      // scores bounded; normalization identical
            se += ex;
            acc[0] = fmaf(ex, va.x, acc[0]); acc[1] = fmaf(ex, va.y, acc[1]);
            acc[2] = fmaf(ex, va.z, acc[2]); acc[3] = fmaf(ex, va.w, acc[3]);
            acc[4] = fmaf(ex, vb.x, acc[4]); acc[5] = fmaf(ex, vb.y, acc[5]);
            acc[6] = fmaf(ex, vb.z, acc[6]); acc[7] = fmaf(ex, vb.w, acc[7]);
        }
        // triangle completion ticket (reads of g_mem/g_k/g_v for t are done)
        int dt = 0;
        if (sub == 0) dt = atomicAdd(&g_tdone[t], 1);

        se += __shfl_xor_sync(gmask, se, 1);
        se += __shfl_xor_sync(gmask, se, 2);
#pragma unroll
        for (int o = 0; o < D_K; o++) {
            acc[o] += __shfl_xor_sync(gmask, acc[o], 1);
            acc[o] += __shfl_xor_sync(gmask, acc[o], 2);
        }
        float inv_se = 1.0f / se;
        float att[D_K];
#pragma unroll
        for (int o = 0; o < D_K; o++) att[o] = acc[o] * inv_se;

        // ---- MLP: this lane owns outputs o = 8*sub .. 8*sub+7 ----
        const int ob = 8 * sub;
        float h[8];
#pragma unroll
        for (int oi = 0; oi < 8; oi++) {
            int o = ob + oi;
            float s = sb1[o];
#pragma unroll
            for (int kk = 0; kk < D_K; kk++) s = fmaf(att[kk], sW1[o * 9 + kk], s);
            h[oi] = s;
        }
        // layernorm 1 + gelu
        {
            float ls = 0.0f;
#pragma unroll
            for (int oi = 0; oi < 8; oi++) ls += h[oi];
            ls += __shfl_xor_sync(gmask, ls, 1);
            ls += __shfl_xor_sync(gmask, ls, 2);
            float mu = ls * (1.0f / H1);
            float lv = 0.0f;
#pragma unroll
            for (int oi = 0; oi < 8; oi++) { float d = h[oi] - mu; lv = fmaf(d, d, lv); }
            lv += __shfl_xor_sync(gmask, lv, 1);
            lv += __shfl_xor_sync(gmask, lv, 2);
            float inv = rsqrtf(lv * (1.0f / H1) + 1e-5f);
#pragma unroll
            for (int oi = 0; oi < 8; oi++)
                h[oi] = gelu_exact((h[oi] - mu) * inv * sg1[ob + oi] + sB1[ob + oi]);
        }
        // rmsnorm -> shared -> linear -> relu -> residual
        {
            float ss = 0.0f;
#pragma unroll
            for (int oi = 0; oi < 8; oi++) ss = fmaf(h[oi], h[oi], ss);
            ss += __shfl_xor_sync(gmask, ss, 1);
            ss += __shfl_xor_sync(gmask, ss, 2);
            float rms = sqrtf(ss * (1.0f / H1));
            float rinv = 1.0f / (rms + 1e-6f);
#pragma unroll
            for (int oi = 0; oi < 8; oi++)
                sh[rl * 33 + ob + oi] = h[oi] * rinv * srw[ob + oi];
            __syncwarp();
#pragma unroll
            for (int oi = 0; oi < 8; oi++) {
                int o = ob + oi;
                float s = sbr[o];
#pragma unroll
                for (int kk = 0; kk < H1; kk++)
                    s = fmaf(sh[rl * 33 + kk], sWr[o * 33 + kk], s);
                h[oi] += fmaxf(s, 0.0f);
            }
        }
        // layernorm 2
        {
            float ls = 0.0f;
#pragma unroll
            for (int oi = 0; oi < 8; oi++) ls += h[oi];
            ls += __shfl_xor_sync(gmask, ls, 1);
            ls += __shfl_xor_sync(gmask, ls, 2);
            float mu = ls * (1.0f / H1);
            float lv = 0.0f;
#pragma unroll
            for (int oi = 0; oi < 8; oi++) { float d = h[oi] - mu; lv = fmaf(d, d, lv); }
            lv += __shfl_xor_sync(gmask, lv, 1);
            lv += __shfl_xor_sync(gmask, lv, 2);
            float inv = rsqrtf(lv * (1.0f / H1) + 1e-5f);
#pragma unroll
            for (int oi = 0; oi < 8; oi++)
                h[oi] = (h[oi] - mu) * inv * sg2[ob + oi] + sB2[ob + oi];
        }
        // publish h, then linear 32->16 + gelu + linear 16->1 (4 outputs/lane)
        __syncwarp();
#pragma unroll
        for (int oi = 0; oi < 8; oi++) sh[rl * 33 + ob + oi] = h[oi];
        __syncwarp();
        float part = 0.0f;
#pragma unroll
        for (int oi = 0; oi < 4; oi++) {
            int o = 4 * sub + oi;
            float s = sb2[o];
#pragma unroll
            for (int kk = 0; kk < H1; kk++)
                s = fmaf(sh[rl * 33 + kk], sW2[o * 33 + kk], s);
            part = fmaf(gelu_exact(s), sW3[o], part);
        }
        part += __shfl_xor_sync(gmask, part, 1);
        part += __shfl_xor_sync(gmask, part, 2);
        // all 4 lanes now hold the full logit
        float lg = part + sb3;

        // ---- publish logit + edge completion ----
        int elast = 0;
        if (sub == 0) {
            g_logits[i] = lg;
            __threadfence();                       // release logit before counting
            int d = atomicAdd(&g_edone[e], 1);
            elast = (d == tot - 1);
            // triangle completion: all members have read g_cnt/g_mem by now
            if (dt == cc - 1) { g_cnt[t] = 0; g_tdone[t] = 0; }
        }
        elast = __shfl_sync(gmask, elast, 0, 4);

        if (elast) {
            __threadfence();                       // acquire all member logits
            int m = min(tot, ECAP);
            float lv[8];
            int   jx[8];
            int   n = 0;
            float mx = -1e30f;
            for (int jj = sub; jj < m; jj += 4) {
                int j = g_emem[e * ECAP + jj];
                float l = g_logits[j];
                jx[n] = j; lv[n] = l; n++;
                mx = fmaxf(mx, l);
            }
            mx = fmaxf(mx, __shfl_xor_sync(gmask, mx, 1));
            mx = fmaxf(mx, __shfl_xor_sync(gmask, mx, 2));
            float s = 0.0f;
            for (int u = 0; u < n; u++) { lv[u] = __expf(lv[u] - mx); s += lv[u]; }
            s += __shfl_xor_sync(gmask, s, 1);
            s += __shfl_xor_sync(gmask, s, 2);
            float inv = 1.0f / s;
            for (int u = 0; u < n; u++) out[jx[u]] = lv[u] * inv;
            if (sub == 0) { g_edone[e] = 0; g_ecnt[e] = 0; }   // ready for next replay
        }
    }
}

extern "C" void kernel_launch(void* const* d_in, const int* in_sizes, int n_in,
                              void* d_out, int out_size) {
    const float* ef   = (const float*)d_in[0];
    const int*   eids = (const int*)  d_in[1];
    const int*   tri  = (const int*)  d_in[2];
    const float* Wq = (const float*)d_in[3];  const float* bq = (const float*)d_in[4];
    const float* Wk = (const float*)d_in[5];  const float* bk = (const float*)d_in[6];
    const float* Wv = (const float*)d_in[7];  const float* bv = (const float*)d_in[8];
    const float* W1 = (const float*)d_in[9];  const float* b1 = (const float*)d_in[10];
    const float* g1 = (const float*)d_in[11]; const float* B1 = (const float*)d_in[12];
    const float* rw = (const float*)d_in[13];
    const float* Wr = (const float*)d_in[14]; const float* br = (const float*)d_in[15];
    const float* g2 = (const float*)d_in[16]; const float* B2 = (const float*)d_in[17];
    const float* W2 = (const float*)d_in[18]; const float* b2 = (const float*)d_in[19];
    const float* W3 = (const float*)d_in[20]; const float* b3 = (const float*)d_in[21];
    float* out = (float*)d_out;

    k_fused<<<NB, TPB>>>(ef, eids, tri, Wq, bq, Wk, bk, Wv, bv,
                         W1, b1, g1, B1, rw, Wr, br, g2, B2, W2, b2, W3, b3, out);
}